// round 11
// baseline (speedup 1.0000x reference)
#include <cuda_runtime.h>
#include <cuda_fp16.h>
#include <cstdint>

#define DD    128
#define NNB   32
#define STRA  144              // nb_s fp32 stride (16 mod 32 -> conflict-free LDS.128 A)
#define WSTR  132              // w_h stride in u32 (half2) units
#define NGRP  4
#define LRELU_ALPHA 0.2f

// w_h : "k-pair row" R = 8c + r (chunk c of 16 k's, r = 0..7):
//   r < 4 : holds half2 pair of physical rows (16c+4r, 16c+4r+1)
//   r >= 4: holds pair of physical rows (16c+4(r-4)+2, +3)
// matched to A fragments read as plain float4 (physical k 4qc..4qc+3).
// within row: pos(e) = (e&7)*16 + (e>>3) (u32 units), conflict-free LDS.128.

__device__ __forceinline__ uint32_t pk_h2(float lo, float hi) {
    __half2 h = __floats2half2_rn(lo, hi);
    return *reinterpret_cast<uint32_t*>(&h);
}

__device__ __forceinline__ void mma_f16(float& c0, float& c1, float& c2, float& c3,
                                        uint32_t a0, uint32_t a1, uint32_t a2, uint32_t a3,
                                        uint32_t b0, uint32_t b1) {
    asm volatile(
        "mma.sync.aligned.m16n8k16.row.col.f32.f16.f16.f32 "
        "{%0,%1,%2,%3}, {%4,%5,%6,%7}, {%8,%9}, {%0,%1,%2,%3};"
        : "+f"(c0), "+f"(c1), "+f"(c2), "+f"(c3)
        : "r"(a0), "r"(a1), "r"(a2), "r"(a3), "r"(b0), "r"(b1));
}

__device__ __forceinline__ void cp_async16(uint32_t smem_addr, const void* gptr) {
    asm volatile("cp.async.cg.shared.global [%0], [%1], 16;\n"
                 :: "r"(smem_addr), "l"(gptr));
}
__device__ __forceinline__ void cp_commit() { asm volatile("cp.async.commit_group;\n" ::); }
__device__ __forceinline__ void cp_wait1()  { asm volatile("cp.async.wait_group 1;\n" ::); }

__device__ __forceinline__ void barg(int id) {
    asm volatile("bar.sync %0, 128;" :: "r"(id) : "memory");
}

extern "C" __global__ void __launch_bounds__(512, 1)
gat_h16c(const float* __restrict__ self_v,
         const float* __restrict__ nbv,
         const float* __restrict__ w,
         const float* __restrict__ q,
         float* __restrict__ out,
         int B)
{
    extern __shared__ float sm[];
    uint32_t* w_h  = reinterpret_cast<uint32_t*>(sm);  // 64*132 = 8448 u32
    float* nb_s    = sm + 64 * WSTR;                   // 4*2*32*144 = 36864 f
    float* self_s  = nb_s + NGRP * 2 * NNB * STRA;     // 1024 f
    float* q_s     = self_s + NGRP * 2 * DD;           // 128 f
    float* scoreP  = q_s + DD;                         // 512 f
    float* hl_s    = scoreP + NGRP * 4 * NNB;          // 4*4*32*2 = 1024 f

    const int t    = threadIdx.x;
    const int lane = t & 31;
    const int ww   = t >> 5;
    const int g    = ww >> 2;
    const int eb   = ww & 3;
    const int gt   = t & 127;
    const int qr   = lane >> 2;
    const int qc   = lane & 3;

    float*  nb_g    = nb_s + g * 2 * NNB * STRA;
    float*  self_g  = self_s + g * 2 * DD;
    float*  scoreG  = scoreP + g * 4 * NNB;
    float2* hl_w    = reinterpret_cast<float2*>(hl_s) + (g * 4 + eb) * NNB;  // warp-private
    const int bid   = g + 1;

    // ---- one-time: w -> fp16 re-paired k rows, fragment-major (RN) ----
    {
        #pragma unroll
        for (int i = 0; i < 16; ++i) {                 // 8192 half2 / 512 thr
            const int fi = t + i * 512;
            const int kp = fi >> 7, e = fi & 127;
            const int c  = kp >> 3, r = kp & 7;
            const int d  = (c << 4) + ((r & 3) << 2) + ((r >> 2) << 1);
            w_h[kp * WSTR + (e & 7) * 16 + (e >> 3)] = pk_h2(w[d * DD + e], w[(d + 1) * DD + e]);
        }
        if (t < DD) q_s[t] = q[t];
    }

    const int stride = gridDim.x * NGRP;
    const int p0     = blockIdx.x * NGRP + g;

    auto issue_tile = [&](int p, int buf) {
        if (p < B) {
            const float4* src = reinterpret_cast<const float4*>(nbv + (size_t)p * NNB * DD);
            const uint32_t dst0 =
                (uint32_t)__cvta_generic_to_shared(nb_g + buf * NNB * STRA);
            #pragma unroll
            for (int i = 0; i < 8; ++i) {              // 1024 float4 / 128 thr
                const int fi = gt + i * 128;
                const int r  = fi >> 5, c4 = fi & 31;
                cp_async16(dst0 + (uint32_t)(r * STRA + 4 * c4) * 4u, src + fi);
            }
            if (gt < 32) {
                const uint32_t ds =
                    (uint32_t)__cvta_generic_to_shared(self_g + buf * DD) + gt * 16u;
                cp_async16(ds, reinterpret_cast<const float4*>(self_v + (size_t)p * DD) + gt);
            }
        }
        cp_commit();
    };

    issue_tile(p0, 0);
    issue_tile(p0 + stride, 1);
    cp_wait1();
    __syncthreads();                // w_h + tile-0 cross-thread visibility (once)

    int it = 0;
    for (int p = p0; p < B; p += stride, ++it) {
        const int cur = it & 1;
        const float* nbuf = nb_g + cur * NNB * STRA;

        // ---- warp-private hi/lo precompute for this warp's 32 cols ----
        // lrelu(s*m)*q == m * (m>=0 ? hi : lo), hi/lo = s>=0 ? {sq,a*sq} : {a*sq,sq}
        {
            const int e  = 32 * eb + lane;
            const float s  = self_g[cur * DD + e];
            const float sq = s * q_s[e];
            const float aq = LRELU_ALPHA * sq;
            hl_w[lane] = (s >= 0.f) ? make_float2(sq, aq) : make_float2(aq, sq);
        }
        __syncwarp();

        // ---- fp16 MMA mainloop: warp tile = 32 rows x 32 cols, k-chunk 16 ----
        float acc[2][4][4];
        #pragma unroll
        for (int T = 0; T < 2; ++T)
            #pragma unroll
            for (int j = 0; j < 4; ++j)
                #pragma unroll
                for (int k = 0; k < 4; ++k) acc[T][j][k] = 0.f;

        const float* ar = nbuf + qr * STRA + 4 * qc;
        const uint32_t* wp = w_h + qc * WSTR + qr * 16 + 4 * eb;

        #pragma unroll
        for (int k0 = 0; k0 < DD; k0 += 16) {
            const float4 A0 = *reinterpret_cast<const float4*>(ar + k0);             // row qr
            const float4 A1 = *reinterpret_cast<const float4*>(ar + 8 * STRA + k0);  // qr+8
            const float4 A2 = *reinterpret_cast<const float4*>(ar + 16 * STRA + k0); // 16+qr
            const float4 A3 = *reinterpret_cast<const float4*>(ar + 24 * STRA + k0); // 24+qr

            const uint32_t a0T0 = pk_h2(A0.x, A0.y);
            const uint32_t a2T0 = pk_h2(A0.z, A0.w);
            const uint32_t a1T0 = pk_h2(A1.x, A1.y);
            const uint32_t a3T0 = pk_h2(A1.z, A1.w);
            const uint32_t a0T1 = pk_h2(A2.x, A2.y);
            const uint32_t a2T1 = pk_h2(A2.z, A2.w);
            const uint32_t a1T1 = pk_h2(A3.x, A3.y);
            const uint32_t a3T1 = pk_h2(A3.z, A3.w);

            const int kp0 = k0 >> 1;
            const uint4 B0 = *reinterpret_cast<const uint4*>(wp + kp0 * WSTR);
            const uint4 B1 = *reinterpret_cast<const uint4*>(wp + (kp0 + 4) * WSTR);

            mma_f16(acc[0][0][0],acc[0][0][1],acc[0][0][2],acc[0][0][3], a0T0,a1T0,a2T0,a3T0, B0.x,B1.x);
            mma_f16(acc[1][0][0],acc[1][0][1],acc[1][0][2],acc[1][0][3], a0T1,a1T1,a2T1,a3T1, B0.x,B1.x);
            mma_f16(acc[0][1][0],acc[0][1][1],acc[0][1][2],acc[0][1][3], a0T0,a1T0,a2T0,a3T0, B0.y,B1.y);
            mma_f16(acc[1][1][0],acc[1][1][1],acc[1][1][2],acc[1][1][3], a0T1,a1T1,a2T1,a3T1, B0.y,B1.y);
            mma_f16(acc[0][2][0],acc[0][2][1],acc[0][2][2],acc[0][2][3], a0T0,a1T0,a2T0,a3T0, B0.z,B1.z);
            mma_f16(acc[1][2][0],acc[1][2][1],acc[1][2][2],acc[1][2][3], a0T1,a1T1,a2T1,a3T1, B0.z,B1.z);
            mma_f16(acc[0][3][0],acc[0][3][1],acc[0][3][2],acc[0][3][3], a0T0,a1T0,a2T0,a3T0, B0.w,B1.w);
            mma_f16(acc[1][3][0],acc[1][3][1],acc[1][3][2],acc[1][3][3], a0T1,a1T1,a2T1,a3T1, B0.w,B1.w);
        }

        // ---- score partials via hi/lo: rows {qr,qr+8,16+qr,24+qr} ----
        {
            float pr[4] = {0.f, 0.f, 0.f, 0.f};
            #pragma unroll
            for (int j = 0; j < 4; ++j) {
                const float2 H0 = hl_w[8 * j + 2 * qc];
                const float2 H1 = hl_w[8 * j + 2 * qc + 1];
                #pragma unroll
                for (int T = 0; T < 2; ++T) {
                    float m;
                    m = acc[T][j][0]; pr[2*T]   = fmaf((m >= 0.f) ? H0.x : H0.y, m, pr[2*T]);
                    m = acc[T][j][1]; pr[2*T]   = fmaf((m >= 0.f) ? H1.x : H1.y, m, pr[2*T]);
                    m = acc[T][j][2]; pr[2*T+1] = fmaf((m >= 0.f) ? H0.x : H0.y, m, pr[2*T+1]);
                    m = acc[T][j][3]; pr[2*T+1] = fmaf((m >= 0.f) ? H1.x : H1.y, m, pr[2*T+1]);
                }
            }
            #pragma unroll
            for (int i = 0; i < 4; ++i) {
                pr[i] += __shfl_xor_sync(0xffffffffu, pr[i], 1);
                pr[i] += __shfl_xor_sync(0xffffffffu, pr[i], 2);
            }
            if (qc == 0) {
                scoreG[eb * NNB + qr]      = pr[0];
                scoreG[eb * NNB + qr + 8]  = pr[1];
                scoreG[eb * NNB + qr + 16] = pr[2];
                scoreG[eb * NNB + qr + 24] = pr[3];
            }
        }
        barg(bid);                          // scores visible; nb[cur] dead (all warps)

        issue_tile(p + 2 * stride, cur);    // refill freed buffer (async)

        // ---- softmax, redundantly in EVERY warp (bit-identical order) ----
        float al0, al1, al2, al3;
        {
            const float s = scoreG[lane] + scoreG[NNB + lane]
                          + scoreG[2 * NNB + lane] + scoreG[3 * NNB + lane];
            float mx = s;
            #pragma unroll
            for (int off = 16; off > 0; off >>= 1)
                mx = fmaxf(mx, __shfl_xor_sync(0xffffffffu, mx, off));
            const float ex = __expf(s - mx);
            float sum = ex;
            #pragma unroll
            for (int off = 16; off > 0; off >>= 1)
                sum += __shfl_xor_sync(0xffffffffu, sum, off);
            const float alpha = ex / sum;    // lane holds alpha[lane]
            al0 = __shfl_sync(0xffffffffu, alpha, qr);
            al1 = __shfl_sync(0xffffffffu, alpha, qr + 8);
            al2 = __shfl_sync(0xffffffffu, alpha, qr + 16);
            al3 = __shfl_sync(0xffffffffu, alpha, qr + 24);
        }

        // ---- register epilogue (before bar2 — fully parallel across warps) ----
        {
            float val[4][2];
            #pragma unroll
            for (int j = 0; j < 4; ++j)
                #pragma unroll
                for (int u = 0; u < 2; ++u) {
                    float v = al0 * acc[0][j][u];
                    v = fmaf(al1, acc[0][j][2 + u], v);
                    v = fmaf(al2, acc[1][j][u], v);
                    v = fmaf(al3, acc[1][j][2 + u], v);
                    v += __shfl_xor_sync(0xffffffffu, v, 4);
                    v += __shfl_xor_sync(0xffffffffu, v, 8);
                    v += __shfl_xor_sync(0xffffffffu, v, 16);
                    val[j][u] = v;
                }
            if (qr == 0) {
                float* op = out + (size_t)p * DD + 32 * eb + 2 * qc;
                #pragma unroll
                for (int j = 0; j < 4; ++j) {
                    op[8 * j]     = val[j][0];
                    op[8 * j + 1] = val[j][1];
                }
            }
        }

        cp_wait1();                         // next tile landed (own-thread view)
        barg(bid);                          // cross-warp visibility of next tile
    }
}

extern "C" void kernel_launch(void* const* d_in, const int* in_sizes, int n_in,
                              void* d_out, int out_size)
{
    const float* self_v = (const float*)d_in[0];   // [B,128]
    const float* nbv    = (const float*)d_in[1];   // [B,32,128]
    const float* w      = (const float*)d_in[2];   // [128,128]
    const float* q      = (const float*)d_in[3];   // [128,1]
    float*       out    = (float*)d_out;           // [B,128]

    const int B = in_sizes[0] / DD;                // 20000

    int smc = 0;
    cudaDeviceGetAttribute(&smc, cudaDevAttrMultiProcessorCount, 0);
    if (smc <= 0) smc = 148;
    int grid = smc;
    if (grid * NGRP > B) grid = (B + NGRP - 1) / NGRP;

    const size_t smem_bytes =
        (size_t)(64 * WSTR + NGRP * 2 * NNB * STRA + NGRP * 2 * DD + DD
                 + NGRP * 4 * NNB + NGRP * 4 * NNB * 2)
        * sizeof(float);                           // ~192 KB

    cudaFuncSetAttribute(gat_h16c, cudaFuncAttributeMaxDynamicSharedMemorySize,
                         (int)smem_bytes);

    gat_h16c<<<grid, 512, smem_bytes>>>(self_v, nbv, w, q, out, B);
}

// round 12
// speedup vs baseline: 1.0919x; 1.0919x over previous
#include <cuda_runtime.h>
#include <cuda_fp16.h>
#include <cstdint>

#define DD    128
#define NNB   32
#define WSTR  132              // w_h stride (u32); fragment-major, re-paired k rows
#define SH    72               // nbH row stride (u32); conflict-free LDS.64/STS.64
#define NGRP  4
#define LRELU_ALPHA 0.2f

// w_h : "k-pair row" R = 8c + r (chunk c of 16 k's, r = 0..7):
//   r < 4 : half2 pair of physical k-rows (16c+4r, 16c+4r+1)
//   r >= 4: pair (16c+4(r-4)+2, +3)
//   within row: pos(e) = (e&7)*16 + (e>>3) (u32), conflict-free LDS.128.
// nbH : row n, entry j = half2( nb[n][2j], nb[n][2j+1] ).  Thread (qr,qc) reads
//   entries {kh+2qc, kh+2qc+1} = physical k 4qc..4qc+3 as ONE LDS.64 -> a0,a2.

__device__ __forceinline__ uint32_t pk_h2(float lo, float hi) {
    __half2 h = __floats2half2_rn(lo, hi);
    return *reinterpret_cast<uint32_t*>(&h);
}

__device__ __forceinline__ void mma_f16(float& c0, float& c1, float& c2, float& c3,
                                        uint32_t a0, uint32_t a1, uint32_t a2, uint32_t a3,
                                        uint32_t b0, uint32_t b1) {
    asm volatile(
        "mma.sync.aligned.m16n8k16.row.col.f32.f16.f16.f32 "
        "{%0,%1,%2,%3}, {%4,%5,%6,%7}, {%8,%9}, {%0,%1,%2,%3};"
        : "+f"(c0), "+f"(c1), "+f"(c2), "+f"(c3)
        : "r"(a0), "r"(a1), "r"(a2), "r"(a3), "r"(b0), "r"(b1));
}

__device__ __forceinline__ void barg(int id) {
    asm volatile("bar.sync %0, 128;" :: "r"(id) : "memory");
}

extern "C" __global__ void __launch_bounds__(512, 1)
gat_h16d(const float* __restrict__ self_v,
         const float* __restrict__ nbv,
         const float* __restrict__ w,
         const float* __restrict__ q,
         float* __restrict__ out,
         int B)
{
    extern __shared__ float sm[];
    uint32_t* w_h   = reinterpret_cast<uint32_t*>(sm);   // 64*132 = 8448 u32
    uint32_t* nbH   = w_h + 64 * WSTR;                   // 4*32*72 = 9216 u32
    float* self_s   = sm + 8448 + 9216;                  // 4*128
    float* q_s      = self_s + NGRP * DD;                // 128
    float* scoreP   = q_s + DD;                          // 4*128
    float* alpha_s  = scoreP + NGRP * 4 * NNB;           // 4*32
    float* hl_s     = alpha_s + NGRP * NNB;              // 4*4*32*2 = 1024

    const int t    = threadIdx.x;
    const int lane = t & 31;
    const int ww   = t >> 5;
    const int g    = ww >> 2;
    const int eb   = ww & 3;
    const int gt   = t & 127;
    const int qr   = lane >> 2;
    const int qc   = lane & 3;

    uint32_t* nbH_g  = nbH + g * 32 * SH;
    float*    self_g = self_s + g * DD;
    float*    scoreG = scoreP + g * 4 * NNB;
    float*    alpha_g = alpha_s + g * NNB;
    float2*   hl_w   = reinterpret_cast<float2*>(hl_s) + (g * 4 + eb) * NNB;
    const int bid    = g + 1;

    // ---- one-time: w -> fp16 re-paired k rows, fragment-major (RN) ----
    {
        #pragma unroll
        for (int i = 0; i < 16; ++i) {                   // 8192 half2 / 512 thr
            const int fi = t + i * 512;
            const int kp = fi >> 7, e = fi & 127;
            const int c  = kp >> 3, r = kp & 7;
            const int d  = (c << 4) + ((r & 3) << 2) + ((r >> 2) << 1);
            w_h[kp * WSTR + (e & 7) * 16 + (e >> 3)] = pk_h2(w[d * DD + e], w[(d + 1) * DD + e]);
        }
        if (t < DD) q_s[t] = q[t];
    }

    const int stride = gridDim.x * NGRP;
    const int p0     = blockIdx.x * NGRP + g;

    // pack 8 float4 (fp32 tile slice) + self float4 into group smem.
    // LDG i of thread gt covers fp32 offsets 512i+4gt -> row 4i+(gt>>5), cols 4*lane..+3
    auto store_tile = [&](const float4* F, const float4& S) {
        const int wrow = gt >> 5;
        #pragma unroll
        for (int i = 0; i < 8; ++i) {
            uint2 hh;
            hh.x = pk_h2(F[i].x, F[i].y);
            hh.y = pk_h2(F[i].z, F[i].w);
            *reinterpret_cast<uint2*>(nbH_g + (4 * i + wrow) * SH + 2 * lane) = hh;
        }
        if (gt < 32)
            *reinterpret_cast<float4*>(self_g + 4 * gt) = S;
    };

    // ---- prologue: convert tile p0 synchronously ----
    if (p0 < B) {
        float4 F[8];
        float4 S = make_float4(0.f, 0.f, 0.f, 0.f);
        const float4* src = reinterpret_cast<const float4*>(nbv + (size_t)p0 * NNB * DD);
        #pragma unroll
        for (int i = 0; i < 8; ++i) F[i] = src[128 * i + gt];
        if (gt < 32) S = reinterpret_cast<const float4*>(self_v + (size_t)p0 * DD)[gt];
        store_tile(F, S);
    }
    __syncthreads();                 // w_h + all groups' tile-0 visible

    for (int p = p0; p < B; p += stride) {
        // ---- step0: issue LDG prefetch for the NEXT batch (regs = 2nd buffer) ----
        const int pn = p + stride;
        const bool have = (pn < B);
        float4 F[8];
        float4 S;
        if (have) {
            const float4* src = reinterpret_cast<const float4*>(nbv + (size_t)pn * NNB * DD);
            #pragma unroll
            for (int i = 0; i < 8; ++i) F[i] = src[128 * i + gt];
            if (gt < 32) S = reinterpret_cast<const float4*>(self_v + (size_t)pn * DD)[gt];
        }

        // ---- step1: warp-private hi/lo for this warp's 32 cols ----
        {
            const int e  = 32 * eb + lane;
            const float s  = self_g[e];
            const float sq = s * q_s[e];
            const float aq = LRELU_ALPHA * sq;
            hl_w[lane] = (s >= 0.f) ? make_float2(sq, aq) : make_float2(aq, sq);
        }
        __syncwarp();

        // ---- step2: fp16 MMA mainloop, warp tile 32x32, zero packing ----
        float acc[2][4][4];
        #pragma unroll
        for (int T = 0; T < 2; ++T)
            #pragma unroll
            for (int j = 0; j < 4; ++j)
                #pragma unroll
                for (int k = 0; k < 4; ++k) acc[T][j][k] = 0.f;

        const uint32_t* arH = nbH_g + qr * SH + 2 * qc;
        const uint32_t* wp  = w_h + qc * WSTR + qr * 16 + 4 * eb;

        #pragma unroll
        for (int k0 = 0; k0 < DD; k0 += 16) {
            const int kh = k0 >> 1;
            const uint2 A0 = *reinterpret_cast<const uint2*>(arH + kh);            // row qr
            const uint2 A1 = *reinterpret_cast<const uint2*>(arH + 8 * SH + kh);   // qr+8
            const uint2 A2 = *reinterpret_cast<const uint2*>(arH + 16 * SH + kh);  // 16+qr
            const uint2 A3 = *reinterpret_cast<const uint2*>(arH + 24 * SH + kh);  // 24+qr
            const uint4 B0 = *reinterpret_cast<const uint4*>(wp + kh * WSTR);
            const uint4 B1 = *reinterpret_cast<const uint4*>(wp + (kh + 4) * WSTR);

            mma_f16(acc[0][0][0],acc[0][0][1],acc[0][0][2],acc[0][0][3], A0.x,A1.x,A0.y,A1.y, B0.x,B1.x);
            mma_f16(acc[1][0][0],acc[1][0][1],acc[1][0][2],acc[1][0][3], A2.x,A3.x,A2.y,A3.y, B0.x,B1.x);
            mma_f16(acc[0][1][0],acc[0][1][1],acc[0][1][2],acc[0][1][3], A0.x,A1.x,A0.y,A1.y, B0.y,B1.y);
            mma_f16(acc[1][1][0],acc[1][1][1],acc[1][1][2],acc[1][1][3], A2.x,A3.x,A2.y,A3.y, B0.y,B1.y);
            mma_f16(acc[0][2][0],acc[0][2][1],acc[0][2][2],acc[0][2][3], A0.x,A1.x,A0.y,A1.y, B0.z,B1.z);
            mma_f16(acc[1][2][0],acc[1][2][1],acc[1][2][2],acc[1][2][3], A2.x,A3.x,A2.y,A3.y, B0.z,B1.z);
            mma_f16(acc[0][3][0],acc[0][3][1],acc[0][3][2],acc[0][3][3], A0.x,A1.x,A0.y,A1.y, B0.w,B1.w);
            mma_f16(acc[1][3][0],acc[1][3][1],acc[1][3][2],acc[1][3][3], A2.x,A3.x,A2.y,A3.y, B0.w,B1.w);
        }

        // ---- step3: score partials via hi/lo ----
        {
            float pr[4] = {0.f, 0.f, 0.f, 0.f};
            #pragma unroll
            for (int j = 0; j < 4; ++j) {
                const float2 H0 = hl_w[8 * j + 2 * qc];
                const float2 H1 = hl_w[8 * j + 2 * qc + 1];
                #pragma unroll
                for (int T = 0; T < 2; ++T) {
                    float m;
                    m = acc[T][j][0]; pr[2*T]   = fmaf((m >= 0.f) ? H0.x : H0.y, m, pr[2*T]);
                    m = acc[T][j][1]; pr[2*T]   = fmaf((m >= 0.f) ? H1.x : H1.y, m, pr[2*T]);
                    m = acc[T][j][2]; pr[2*T+1] = fmaf((m >= 0.f) ? H0.x : H0.y, m, pr[2*T+1]);
                    m = acc[T][j][3]; pr[2*T+1] = fmaf((m >= 0.f) ? H1.x : H1.y, m, pr[2*T+1]);
                }
            }
            #pragma unroll
            for (int i = 0; i < 4; ++i) {
                pr[i] += __shfl_xor_sync(0xffffffffu, pr[i], 1);
                pr[i] += __shfl_xor_sync(0xffffffffu, pr[i], 2);
            }
            if (qc == 0) {
                scoreG[eb * NNB + qr]      = pr[0];
                scoreG[eb * NNB + qr + 8]  = pr[1];
                scoreG[eb * NNB + qr + 16] = pr[2];
                scoreG[eb * NNB + qr + 24] = pr[3];
            }
        }
        barg(bid);                     // scores visible; nbH_g/self_g dead

        // ---- step5: pack + store NEXT tile into the (single) group buffer ----
        if (have) store_tile(F, S);

        // ---- step6: softmax over 32 neighbors (warp 0 of group) ----
        if (eb == 0) {
            const float s = scoreG[lane] + scoreG[NNB + lane]
                          + scoreG[2 * NNB + lane] + scoreG[3 * NNB + lane];
            float mx = s;
            #pragma unroll
            for (int off = 16; off > 0; off >>= 1)
                mx = fmaxf(mx, __shfl_xor_sync(0xffffffffu, mx, off));
            const float ex = __expf(s - mx);
            float sum = ex;
            #pragma unroll
            for (int off = 16; off > 0; off >>= 1)
                sum += __shfl_xor_sync(0xffffffffu, sum, off);
            alpha_g[lane] = ex / sum;
        }
        barg(bid);                     // alpha + next tile visible

        // ---- step8: register epilogue, alpha from smem, direct STG ----
        {
            const float al0 = alpha_g[qr];
            const float al1 = alpha_g[qr + 8];
            const float al2 = alpha_g[qr + 16];
            const float al3 = alpha_g[qr + 24];
            float val[4][2];
            #pragma unroll
            for (int j = 0; j < 4; ++j)
                #pragma unroll
                for (int u = 0; u < 2; ++u) {
                    float v = al0 * acc[0][j][u];
                    v = fmaf(al1, acc[0][j][2 + u], v);
                    v = fmaf(al2, acc[1][j][u], v);
                    v = fmaf(al3, acc[1][j][2 + u], v);
                    v += __shfl_xor_sync(0xffffffffu, v, 4);
                    v += __shfl_xor_sync(0xffffffffu, v, 8);
                    v += __shfl_xor_sync(0xffffffffu, v, 16);
                    val[j][u] = v;
                }
            if (qr == 0) {
                float* op = out + (size_t)p * DD + 32 * eb + 2 * qc;
                #pragma unroll
                for (int j = 0; j < 4; ++j) {
                    op[8 * j]     = val[j][0];
                    op[8 * j + 1] = val[j][1];
                }
            }
        }
    }
}

extern "C" void kernel_launch(void* const* d_in, const int* in_sizes, int n_in,
                              void* d_out, int out_size)
{
    const float* self_v = (const float*)d_in[0];   // [B,128]
    const float* nbv    = (const float*)d_in[1];   // [B,32,128]
    const float* w      = (const float*)d_in[2];   // [128,128]
    const float* q      = (const float*)d_in[3];   // [128,1]
    float*       out    = (float*)d_out;           // [B,128]

    const int B = in_sizes[0] / DD;                // 20000

    int smc = 0;
    cudaDeviceGetAttribute(&smc, cudaDevAttrMultiProcessorCount, 0);
    if (smc <= 0) smc = 148;
    int grid = smc;
    if (grid * NGRP > B) grid = (B + NGRP - 1) / NGRP;

    const size_t smem_bytes =
        (size_t)(64 * WSTR + NGRP * 32 * SH            // u32 regions (w_h, nbH)
                 + NGRP * DD + DD                      // self_s, q_s
                 + NGRP * 4 * NNB + NGRP * NNB         // scoreP, alpha_s
                 + NGRP * 4 * NNB * 2)                 // hl_s
        * 4;                                           // 79,872 B

    cudaFuncSetAttribute(gat_h16d, cudaFuncAttributeMaxDynamicSharedMemorySize,
                         (int)smem_bytes);

    gat_h16d<<<grid, 512, smem_bytes>>>(self_v, nbv, w, q, out, B);
}